// round 1
// baseline (speedup 1.0000x reference)
#include <cuda_runtime.h>

// AdaMoeLayer: B=8, S=4096, D=512, E=8  ->  T = 32768 tokens
// out[t] = sum_e w[t,e] * (x[t] @ W_exp[e] + b_exp[e])
// w from softmax gate minus adaptive sigmoid threshold, renormalized.

#define D_DIM 512
#define E_DIM 8
#define T_MAX 32768
#define MAX_THRESHOLD 0.25f

// scratch for per-token expert weights [T, E]  (1 MB, static device array per rules)
__device__ float g_w[T_MAX * E_DIM];

// ---------------------------------------------------------------------------
// Kernel 1: gating.  One warp per token.
// ---------------------------------------------------------------------------
__global__ __launch_bounds__(256) void gating_kernel(
    const float* __restrict__ x,      // [T, D]
    const float* __restrict__ Wg,     // [D, E]
    const float* __restrict__ bg,     // [E]
    const float* __restrict__ Wt,     // [D, 1]
    const float* __restrict__ bt,     // [1]
    int T)
{
    __shared__ float sWg[E_DIM][D_DIM];  // [e][d] so lane-strided reads are conflict-free
    __shared__ float sWt[D_DIM];

    const int tid = threadIdx.x;

    // stage gate weights into shared
    for (int i = tid; i < E_DIM * D_DIM; i += 256) {
        int e = i / D_DIM;
        int d = i - e * D_DIM;
        sWg[e][d] = Wg[d * E_DIM + e];
    }
    for (int i = tid; i < D_DIM; i += 256) sWt[i] = Wt[i];
    __syncthreads();

    const int warp = tid >> 5;
    const int lane = tid & 31;
    const int t = blockIdx.x * 8 + warp;
    if (t >= T) return;

    const float* xr = x + (size_t)t * D_DIM;

    float acc[9];
#pragma unroll
    for (int e = 0; e < 9; e++) acc[e] = 0.f;

#pragma unroll
    for (int i = 0; i < D_DIM / 32; i++) {
        int d = lane + 32 * i;
        float xv = xr[d];
#pragma unroll
        for (int e = 0; e < E_DIM; e++) acc[e] = fmaf(xv, sWg[e][d], acc[e]);
        acc[8] = fmaf(xv, sWt[d], acc[8]);
    }

    // butterfly reduce all 9 sums across the warp
#pragma unroll
    for (int off = 16; off > 0; off >>= 1) {
#pragma unroll
        for (int e = 0; e < 9; e++) acc[e] += __shfl_xor_sync(0xffffffffu, acc[e], off);
    }

    // every lane redundantly computes softmax / threshold / renorm
    float logit[E_DIM];
#pragma unroll
    for (int e = 0; e < E_DIM; e++) logit[e] = acc[e] + bg[e];

    float m = logit[0];
#pragma unroll
    for (int e = 1; e < E_DIM; e++) m = fmaxf(m, logit[e]);

    float p[E_DIM];
    float s = 0.f;
#pragma unroll
    for (int e = 0; e < E_DIM; e++) { p[e] = expf(logit[e] - m); s += p[e]; }
    float inv_s = 1.f / s;

    float thr_logit = acc[8] + bt[0];
    float thr = (1.f / (1.f + expf(-thr_logit))) * MAX_THRESHOLD;

    float w[E_DIM];
    float ws = 0.f;
#pragma unroll
    for (int e = 0; e < E_DIM; e++) {
        float a = p[e] * inv_s - thr;
        w[e] = (a >= 0.f) ? a : 0.f;
        ws += w[e];
    }
    if (ws == 0.f) ws = 1.f;   // exact-compare, matches reference
    float inv_ws = 1.f / ws;

    // lane e writes weight e (unrolled select avoids local-memory indexing)
    if (lane < E_DIM) {
        float v = 0.f;
#pragma unroll
        for (int e = 0; e < E_DIM; e++) if (lane == e) v = w[e];
        g_w[t * E_DIM + lane] = v * inv_ws;
    }
}

// ---------------------------------------------------------------------------
// Kernel 2: fused weighted expert GEMM.
// BM=128, BN=64, BK=16, 256 threads, each thread computes 8x4 outputs.
// For each expert: acc = X_tile @ We_tile over full K; out += w_e*(acc + b_e).
// ---------------------------------------------------------------------------
#define BM 128
#define BN 64
#define BK 16

__global__ __launch_bounds__(256) void moe_gemm_kernel(
    const float* __restrict__ X,     // [T, D]
    const float* __restrict__ Wexp,  // [E, D, D]
    const float* __restrict__ bexp,  // [E, D]
    float* __restrict__ out,         // [T, D]
    int T)
{
    __shared__ float Xs[BK][BM];
    __shared__ float Ws[BK][BN];
    __shared__ float sw[BM * E_DIM];   // token weights for this M tile
    __shared__ float sb[E_DIM][BN];    // bias slice for this N tile

    const int tid  = threadIdx.x;
    const int bx   = blockIdx.x;             // N tile (0..7)
    const int by   = blockIdx.y;             // M tile
    const int row0 = by * BM;
    const int col0 = bx * BN;

    // stage per-token weights (contiguous copy) and bias slice
    for (int i = tid; i < BM * E_DIM; i += 256) sw[i] = g_w[row0 * E_DIM + i];
    for (int i = tid; i < E_DIM * BN; i += 256) {
        int e = i / BN;
        int n = i - e * BN;
        sb[e][n] = bexp[e * D_DIM + col0 + n];
    }

    const int tx = tid & 15;                 // 0..15 -> 4 cols each
    const int ty = tid >> 4;                 // 0..15 -> 8 rows each

    // X tile loader mapping: each thread loads 8 floats (2x float4) of one row
    const int lm = tid & 127;                // row within tile
    const int lk = (tid >> 7) * 8;           // 0 or 8: k offset

    // W tile loader mapping: float4 per thread
    const int wk = tid >> 4;                 // 0..15
    const int wn = (tid & 15) * 4;           // 0..60

    float o[8][4];
#pragma unroll
    for (int i = 0; i < 8; i++)
#pragma unroll
        for (int j = 0; j < 4; j++) o[i][j] = 0.f;

#pragma unroll 1
    for (int e = 0; e < E_DIM; e++) {
        float acc[8][4];
#pragma unroll
        for (int i = 0; i < 8; i++)
#pragma unroll
            for (int j = 0; j < 4; j++) acc[i][j] = 0.f;

        const float* We = Wexp + (size_t)e * D_DIM * D_DIM;

#pragma unroll 1
        for (int kt = 0; kt < D_DIM / BK; kt++) {
            __syncthreads();
            // load X tile (transposed into Xs[k][m])
            {
                const float* xg = X + (size_t)(row0 + lm) * D_DIM + kt * BK + lk;
                float4 a0 = *reinterpret_cast<const float4*>(xg);
                float4 a1 = *reinterpret_cast<const float4*>(xg + 4);
                Xs[lk + 0][lm] = a0.x;
                Xs[lk + 1][lm] = a0.y;
                Xs[lk + 2][lm] = a0.z;
                Xs[lk + 3][lm] = a0.w;
                Xs[lk + 4][lm] = a1.x;
                Xs[lk + 5][lm] = a1.y;
                Xs[lk + 6][lm] = a1.z;
                Xs[lk + 7][lm] = a1.w;
            }
            // load W tile
            {
                const float* wg = We + (size_t)(kt * BK + wk) * D_DIM + col0 + wn;
                *reinterpret_cast<float4*>(&Ws[wk][wn]) =
                    *reinterpret_cast<const float4*>(wg);
            }
            __syncthreads();

#pragma unroll
            for (int kk = 0; kk < BK; kk++) {
                float4 xv0 = *reinterpret_cast<const float4*>(&Xs[kk][ty * 8]);
                float4 xv1 = *reinterpret_cast<const float4*>(&Xs[kk][ty * 8 + 4]);
                float4 wv  = *reinterpret_cast<const float4*>(&Ws[kk][tx * 4]);
                float xr[8] = {xv0.x, xv0.y, xv0.z, xv0.w, xv1.x, xv1.y, xv1.z, xv1.w};
                float wr[4] = {wv.x, wv.y, wv.z, wv.w};
#pragma unroll
                for (int i = 0; i < 8; i++)
#pragma unroll
                    for (int j = 0; j < 4; j++)
                        acc[i][j] = fmaf(xr[i], wr[j], acc[i][j]);
            }
        }

        // epilogue for this expert: out += w_e * (acc + b_e)
#pragma unroll
        for (int i = 0; i < 8; i++) {
            float we = sw[(ty * 8 + i) * E_DIM + e];
#pragma unroll
            for (int j = 0; j < 4; j++)
                o[i][j] = fmaf(we, acc[i][j] + sb[e][tx * 4 + j], o[i][j]);
        }
    }

    // write output tile
#pragma unroll
    for (int i = 0; i < 8; i++) {
        float4 v = make_float4(o[i][0], o[i][1], o[i][2], o[i][3]);
        *reinterpret_cast<float4*>(out + (size_t)(row0 + ty * 8 + i) * D_DIM + col0 + tx * 4) = v;
    }
}

// ---------------------------------------------------------------------------
extern "C" void kernel_launch(void* const* d_in, const int* in_sizes, int n_in,
                              void* d_out, int out_size)
{
    const float* x    = (const float*)d_in[0];  // [T, 512]
    const float* Wg   = (const float*)d_in[1];  // [512, 8]
    const float* bg   = (const float*)d_in[2];  // [8]
    const float* Wt   = (const float*)d_in[3];  // [512, 1]
    const float* bt   = (const float*)d_in[4];  // [1]
    const float* Wexp = (const float*)d_in[5];  // [8, 512, 512]
    const float* bexp = (const float*)d_in[6];  // [8, 512]
    float* out        = (float*)d_out;          // [T, 512]

    const int T = in_sizes[0] / D_DIM;          // 32768

    gating_kernel<<<T / 8, 256>>>(x, Wg, bg, Wt, bt, T);

    dim3 grid(D_DIM / BN, T / BM);              // (8, 256)
    moe_gemm_kernel<<<grid, 256>>>(x, Wexp, bexp, out, T);
}

// round 3
// speedup vs baseline: 3.9313x; 3.9313x over previous
#include <cuda_runtime.h>
#include <cstdint>

// AdaMoeLayer: out[t] = sum_e w[t,e]*(x[t] @ W_e + b_e),  T=32768, D=512, E=8.
// tf32 mma.sync (target-portable HMMA), w folded into A fragments at load time,
// single fp32 accumulator over all experts and K. No tcgen05 (ptxas target is
// plain sm_103, arch-accelerated features unavailable).

#define D_DIM 512
#define E_DIM 8
#define T_TOK 32768
#define MAX_THRESHOLD 0.25f

// ---- static device scratch ----
__device__ float g_w[T_TOK * E_DIM];                     // gate weights [t][e], 1 MB
__device__ float g_Wt[(size_t)E_DIM * D_DIM * D_DIM];    // tf32-rounded W, 8 MB

// ---------------------------------------------------------------------------
// helpers
// ---------------------------------------------------------------------------
__device__ __forceinline__ uint32_t smem_u32(const void* p) {
    uint32_t a;
    asm("{ .reg .u64 t; cvta.to.shared.u64 t, %1; cvt.u32.u64 %0, t; }"
        : "=r"(a) : "l"(p));
    return a;
}
__device__ __forceinline__ void cp16(uint32_t dst, const void* src) {
    asm volatile("cp.async.cg.shared.global [%0], [%1], 16;\n"
                 :: "r"(dst), "l"(__cvta_generic_to_global(src)) : "memory");
}
__device__ __forceinline__ uint32_t cvt_tf32(float x) {
    uint32_t u;
    asm("cvt.rna.tf32.f32 %0, %1;" : "=r"(u) : "f"(x));
    return u;
}
__device__ __forceinline__ void mma_tf32(float* c, const uint32_t* a, const uint32_t* b) {
    asm volatile(
        "mma.sync.aligned.m16n8k8.row.col.f32.tf32.tf32.f32 "
        "{%0,%1,%2,%3}, {%4,%5,%6,%7}, {%8,%9}, {%0,%1,%2,%3};"
        : "+f"(c[0]), "+f"(c[1]), "+f"(c[2]), "+f"(c[3])
        : "r"(a[0]), "r"(a[1]), "r"(a[2]), "r"(a[3]), "r"(b[0]), "r"(b[1]));
}

// ---------------------------------------------------------------------------
// Kernel 1: gating. One warp per token. (exact fp32, matches reference)
// ---------------------------------------------------------------------------
__global__ __launch_bounds__(256) void gating_kernel(
    const float* __restrict__ x,
    const float* __restrict__ Wg, const float* __restrict__ bg,
    const float* __restrict__ Wt, const float* __restrict__ bt)
{
    __shared__ float sWg[E_DIM][D_DIM];
    __shared__ float sWt[D_DIM];
    const int tid = threadIdx.x;
    for (int i = tid; i < E_DIM * D_DIM; i += 256) {
        int e = i / D_DIM, d = i - e * D_DIM;
        sWg[e][d] = Wg[d * E_DIM + e];
    }
    for (int i = tid; i < D_DIM; i += 256) sWt[i] = Wt[i];
    __syncthreads();

    const int warp = tid >> 5, lane = tid & 31;
    const int t = blockIdx.x * 8 + warp;
    const float* xr = x + (size_t)t * D_DIM;

    float acc[9];
#pragma unroll
    for (int e = 0; e < 9; e++) acc[e] = 0.f;
#pragma unroll
    for (int i = 0; i < D_DIM / 32; i++) {
        int d = lane + 32 * i;
        float xv = xr[d];
#pragma unroll
        for (int e = 0; e < E_DIM; e++) acc[e] = fmaf(xv, sWg[e][d], acc[e]);
        acc[8] = fmaf(xv, sWt[d], acc[8]);
    }
#pragma unroll
    for (int off = 16; off > 0; off >>= 1)
#pragma unroll
        for (int e = 0; e < 9; e++) acc[e] += __shfl_xor_sync(0xffffffffu, acc[e], off);

    float logit[E_DIM];
#pragma unroll
    for (int e = 0; e < E_DIM; e++) logit[e] = acc[e] + bg[e];
    float m = logit[0];
#pragma unroll
    for (int e = 1; e < E_DIM; e++) m = fmaxf(m, logit[e]);
    float p[E_DIM], s = 0.f;
#pragma unroll
    for (int e = 0; e < E_DIM; e++) { p[e] = expf(logit[e] - m); s += p[e]; }
    float inv_s = 1.f / s;
    float thr = (1.f / (1.f + expf(-(acc[8] + bt[0])))) * MAX_THRESHOLD;

    float w[E_DIM], ws = 0.f;
#pragma unroll
    for (int e = 0; e < E_DIM; e++) {
        float a = p[e] * inv_s - thr;
        w[e] = (a >= 0.f) ? a : 0.f;
        ws += w[e];
    }
    if (ws == 0.f) ws = 1.f;
    float inv_ws = 1.f / ws;

    if (lane < E_DIM) {
        float v = 0.f;
#pragma unroll
        for (int e = 0; e < E_DIM; e++) if (lane == e) v = w[e];
        g_w[t * E_DIM + lane] = v * inv_ws;
    }
}

// ---------------------------------------------------------------------------
// Kernel 2: pre-round W_exp to tf32 precision (stored as fp32 bits).
// ---------------------------------------------------------------------------
__global__ __launch_bounds__(256) void wprep_kernel(const float* __restrict__ W)
{
    size_t i = ((size_t)blockIdx.x * 256 + threadIdx.x) * 4;
    const size_t N = (size_t)E_DIM * D_DIM * D_DIM;
    if (i >= N) return;
    float4 v = *reinterpret_cast<const float4*>(W + i);
    uint4 o;
    o.x = cvt_tf32(v.x); o.y = cvt_tf32(v.y);
    o.z = cvt_tf32(v.z); o.w = cvt_tf32(v.w);
    *reinterpret_cast<uint4*>(g_Wt + i) = o;
}

// ---------------------------------------------------------------------------
// Kernel 3: main GEMM.  Grid (4 N-tiles, 256 M-tiles), 512 threads.
// CTA tile 128x128; 16 warps (4x4); warp tile 32x32 (2 m16 x 4 n8).
// K-chunks of 16 over K=512; experts looped inside each chunk.
// ---------------------------------------------------------------------------
#define XS_STRIDE 20      // floats per Xs row (80 B, conflict-free + 16B aligned)
#define BS_STRIDE 136     // floats per Bs row (544 B)
#define XS_WORDS (128 * XS_STRIDE)          // 2560
#define BS_E_WORDS (16 * BS_STRIDE)         // 2176
#define BS_WORDS (E_DIM * BS_E_WORDS)       // 17408
#define SW_OFF 0
#define BB_OFF 1024
#define XS_OFF 2048
#define BS_OFF (XS_OFF + 2 * XS_WORDS)      // 7168
#define SMEM_WORDS (BS_OFF + 2 * BS_WORDS)  // 41984
#define SMEM_BYTES (SMEM_WORDS * 4)         // 167936

__device__ __forceinline__ void issue_stage(
    int tid, uint32_t sm_base, float* smem, int buf, int kt, int t0, int n0,
    const float* __restrict__ X)
{
    // X tile: 128 rows x 4 chunks of 16B
    {
        int row = tid >> 2, ch = tid & 3;
        uint32_t dst = sm_base + (XS_OFF + buf * XS_WORDS + row * XS_STRIDE) * 4 + ch * 16;
        cp16(dst, X + (size_t)(t0 + row) * D_DIM + kt * 16 + ch * 4);
    }
    // B tiles: 8 experts x 16 rows x 32 chunks
    {
        int row = tid >> 5, ch = tid & 31;
#pragma unroll
        for (int e = 0; e < E_DIM; e++) {
            uint32_t dst = sm_base +
                (BS_OFF + buf * BS_WORDS + e * BS_E_WORDS + row * BS_STRIDE) * 4 + ch * 16;
            cp16(dst, g_Wt + ((size_t)e * D_DIM + kt * 16 + row) * D_DIM + n0 + ch * 4);
        }
    }
    asm volatile("cp.async.commit_group;\n" ::: "memory");
}

__global__ __launch_bounds__(512, 1) void moe_mma_kernel(
    const float* __restrict__ X,
    const float* __restrict__ bexp,
    float* __restrict__ out)
{
    extern __shared__ float smem[];
    const uint32_t sm_base = smem_u32(smem);
    const int tid = threadIdx.x;
    const int lane = tid & 31, wid = tid >> 5;
    const int g = lane >> 2, t4 = lane & 3;
    const int wm = (wid >> 2) * 32, wn = (wid & 3) * 32;
    const int n0 = blockIdx.x * 128;
    const int t0 = blockIdx.y * 128;

    // stage gate weights (transposed to [e][m]) and bias slice [e][n]
    for (int i = tid; i < 128 * E_DIM; i += 512) {
        int m = i >> 3, e = i & 7;
        smem[SW_OFF + e * 128 + m] = g_w[(size_t)(t0 + m) * E_DIM + e];
    }
    for (int i = tid; i < E_DIM * 128; i += 512) {
        int e = i >> 7, c = i & 127;
        smem[BB_OFF + i] = bexp[e * D_DIM + n0 + c];
    }

    float acc[2][4][4];
#pragma unroll
    for (int mt = 0; mt < 2; mt++)
#pragma unroll
        for (int nt = 0; nt < 4; nt++)
#pragma unroll
            for (int j = 0; j < 4; j++) acc[mt][nt][j] = 0.f;

    issue_stage(tid, sm_base, smem, 0, 0, t0, n0, X);

#pragma unroll 1
    for (int kt = 0; kt < 32; ++kt) {
        const int buf = kt & 1;
        __syncthreads();   // everyone done with buf^1 (chunk kt-1)
        if (kt + 1 < 32) issue_stage(tid, sm_base, smem, buf ^ 1, kt + 1, t0, n0, X);
        if (kt + 1 < 32) asm volatile("cp.async.wait_group 1;\n" ::: "memory");
        else             asm volatile("cp.async.wait_group 0;\n" ::: "memory");
        __syncthreads();   // chunk kt visible to all

        const float* Xb = smem + XS_OFF + buf * XS_WORDS;
        const float* Bb = smem + BS_OFF + buf * BS_WORDS;

#pragma unroll
        for (int k8 = 0; k8 < 16; k8 += 8) {
            // raw A fragments (reused across experts)
            float ar[2][4];
#pragma unroll
            for (int mt = 0; mt < 2; mt++) {
                int r = wm + mt * 16 + g;
                ar[mt][0] = Xb[r * XS_STRIDE + k8 + t4];
                ar[mt][1] = Xb[(r + 8) * XS_STRIDE + k8 + t4];
                ar[mt][2] = Xb[r * XS_STRIDE + k8 + t4 + 4];
                ar[mt][3] = Xb[(r + 8) * XS_STRIDE + k8 + t4 + 4];
            }
#pragma unroll
            for (int e = 0; e < E_DIM; e++) {
                // per-row gate scales
                float s00 = smem[SW_OFF + e * 128 + wm + g];
                float s01 = smem[SW_OFF + e * 128 + wm + g + 8];
                float s10 = smem[SW_OFF + e * 128 + wm + 16 + g];
                float s11 = smem[SW_OFF + e * 128 + wm + 16 + g + 8];
                uint32_t a[2][4];
                a[0][0] = cvt_tf32(ar[0][0] * s00);
                a[0][1] = cvt_tf32(ar[0][1] * s01);
                a[0][2] = cvt_tf32(ar[0][2] * s00);
                a[0][3] = cvt_tf32(ar[0][3] * s01);
                a[1][0] = cvt_tf32(ar[1][0] * s10);
                a[1][1] = cvt_tf32(ar[1][1] * s11);
                a[1][2] = cvt_tf32(ar[1][2] * s10);
                a[1][3] = cvt_tf32(ar[1][3] * s11);

                const float* Be = Bb + e * BS_E_WORDS;
                uint32_t b[4][2];
#pragma unroll
                for (int nt = 0; nt < 4; nt++) {
                    int n = wn + nt * 8 + g;
                    b[nt][0] = __float_as_uint(Be[(k8 + t4) * BS_STRIDE + n]);
                    b[nt][1] = __float_as_uint(Be[(k8 + t4 + 4) * BS_STRIDE + n]);
                }
#pragma unroll
                for (int mt = 0; mt < 2; mt++)
#pragma unroll
                    for (int nt = 0; nt < 4; nt++)
                        mma_tf32(acc[mt][nt], a[mt], b[nt]);
            }
        }
    }

    __syncthreads();

    // ---- epilogue: add sum_e w_te * b_e[n], write out ----
#pragma unroll
    for (int mt = 0; mt < 2; mt++) {
#pragma unroll
        for (int rr = 0; rr < 2; rr++) {
            int row = wm + mt * 16 + g + rr * 8;
            float wv[E_DIM];
#pragma unroll
            for (int e = 0; e < E_DIM; e++) wv[e] = smem[SW_OFF + e * 128 + row];
#pragma unroll
            for (int nt = 0; nt < 4; nt++) {
                int cl = wn + nt * 8 + 2 * t4;
                float b0 = 0.f, b1 = 0.f;
#pragma unroll
                for (int e = 0; e < E_DIM; e++) {
                    b0 = fmaf(wv[e], smem[BB_OFF + e * 128 + cl], b0);
                    b1 = fmaf(wv[e], smem[BB_OFF + e * 128 + cl + 1], b1);
                }
                float2 v;
                v.x = acc[mt][nt][rr * 2 + 0] + b0;
                v.y = acc[mt][nt][rr * 2 + 1] + b1;
                *reinterpret_cast<float2*>(out + (size_t)(t0 + row) * D_DIM + n0 + cl) = v;
            }
        }
    }
}

// ---------------------------------------------------------------------------
extern "C" void kernel_launch(void* const* d_in, const int* in_sizes, int n_in,
                              void* d_out, int out_size)
{
    const float* x    = (const float*)d_in[0];  // [T, 512]
    const float* Wg   = (const float*)d_in[1];  // [512, 8]
    const float* bg   = (const float*)d_in[2];  // [8]
    const float* Wt   = (const float*)d_in[3];  // [512, 1]
    const float* bt   = (const float*)d_in[4];  // [1]
    const float* Wexp = (const float*)d_in[5];  // [8, 512, 512]
    const float* bexp = (const float*)d_in[6];  // [8, 512]
    float* out        = (float*)d_out;          // [T, 512]

    const int T = in_sizes[0] / D_DIM;          // 32768

    static bool attr_set = false;
    if (!attr_set) {
        cudaFuncSetAttribute(moe_mma_kernel,
                             cudaFuncAttributeMaxDynamicSharedMemorySize, SMEM_BYTES);
        attr_set = true;
    }

    gating_kernel<<<T / 8, 256>>>(x, Wg, bg, Wt, bt);
    wprep_kernel<<<(E_DIM * D_DIM * D_DIM / 4 + 255) / 256, 256>>>(Wexp);
    moe_mma_kernel<<<dim3(4, T / 128), 512, SMEM_BYTES>>>(x, bexp, out);
}